// round 13
// baseline (speedup 1.0000x reference)
#include <cuda_runtime.h>
#include <cuda_bf16.h>
#include <math.h>
#include <stdint.h>

#define BN 131072
#define DD 256
#define NBLK (BN / 64)

// ---------------- scratch (device globals: allocation-free) ----------------
__device__ __align__(16) short       g_hs1[(size_t)BN * DD];   // layer0 out (int16, exact)
__device__ __align__(16) short       g_hs2[(size_t)BN * DD];   // layer1 out
__device__ float                     g_mu[3][BN];
__device__ float                     g_rstd[3][BN];
__device__ unsigned                  g_gamma[3];
__device__ float                     g_beta[3];
__device__ __align__(16) signed char g_wb[3][DD * DD];         // +-1 int8, swizzled [n][k] layout

__device__ __forceinline__ uint32_t smem_u32(const void* p) {
    uint32_t a;
    asm("{ .reg .u64 t; cvta.to.shared.u64 t, %1; cvt.u32.u64 %0, t; }" : "=r"(a) : "l"(p));
    return a;
}

// ---------------- init ----------------
__global__ void init_kernel() {
    if (threadIdx.x < 3) g_gamma[threadIdx.x] = 0u;
}

// ---------------- weight prep: alpha/beta + sign -> swizzled int8 ---------
__global__ void __launch_bounds__(1024) wprep_kernel(const float* __restrict__ W1,
                                                     const float* __restrict__ W2,
                                                     const float* __restrict__ W3) {
    const float* W = blockIdx.x == 0 ? W1 : (blockIdx.x == 1 ? W2 : W3);
    __shared__ float ps[32], pa[32];
    __shared__ float s_alpha;
    int tid = threadIdx.x;
    float s = 0.f, sa = 0.f;
    for (int i = tid; i < DD * DD; i += 1024) {
        float w = W[i];
        s += w; sa += fabsf(w);
    }
#pragma unroll
    for (int o = 16; o; o >>= 1) {
        s  += __shfl_xor_sync(0xffffffffu, s,  o);
        sa += __shfl_xor_sync(0xffffffffu, sa, o);
    }
    if ((tid & 31) == 0) { ps[tid >> 5] = s; pa[tid >> 5] = sa; }
    __syncthreads();
    if (tid == 0) {
        float ts = 0.f, ta = 0.f;
        for (int i = 0; i < 32; i++) { ts += ps[i]; ta += pa[i]; }  // fixed order
        float alpha = ts / 65536.0f;
        g_beta[blockIdx.x] = fmaxf(ta / 65536.0f, 1e-8f);
        s_alpha = alpha;
    }
    __syncthreads();
    float alpha = s_alpha;
    signed char* wb = g_wb[blockIdx.x];
    for (int i = tid; i < DD * DD; i += 1024) {
        int n = i >> 8, k = i & 255;
        signed char v = ((W[i] - alpha) > 0.f) ? (signed char)1 : (signed char)-1;
        unsigned off = (unsigned)n * 256u + ((((unsigned)k >> 4) ^ ((unsigned)n & 7u)) << 4) + ((unsigned)k & 15u);
        wb[off] = v;
    }
}

// ---------------- stats for x: per-row mu/rstd + global gamma[0] ----------
__global__ void __launch_bounds__(256) stats_kernel(const float* __restrict__ x) {
    __shared__ unsigned sg;
    int tid = threadIdx.x;
    if (tid == 0) sg = 0u;
    __syncthreads();
    int warp = tid >> 5, lane = tid & 31;
    size_t row = (size_t)blockIdx.x * 8 + warp;
    const float* xr = x + row * DD;
    float4 a = *(const float4*)(xr + lane * 4);
    float4 b = *(const float4*)(xr + 128 + lane * 4);
    float s = ((a.x + a.y) + (a.z + a.w)) + ((b.x + b.y) + (b.z + b.w));
#pragma unroll
    for (int o = 16; o; o >>= 1) s += __shfl_xor_sync(0xffffffffu, s, o);
    float mu = s * (1.0f / 256.0f);
    float ss = 0.f, mx = 0.f, d;
    d = a.x - mu; ss += d * d; mx = fmaxf(mx, fabsf(d));
    d = a.y - mu; ss += d * d; mx = fmaxf(mx, fabsf(d));
    d = a.z - mu; ss += d * d; mx = fmaxf(mx, fabsf(d));
    d = a.w - mu; ss += d * d; mx = fmaxf(mx, fabsf(d));
    d = b.x - mu; ss += d * d; mx = fmaxf(mx, fabsf(d));
    d = b.y - mu; ss += d * d; mx = fmaxf(mx, fabsf(d));
    d = b.z - mu; ss += d * d; mx = fmaxf(mx, fabsf(d));
    d = b.w - mu; ss += d * d; mx = fmaxf(mx, fabsf(d));
#pragma unroll
    for (int o = 16; o; o >>= 1) {
        ss += __shfl_xor_sync(0xffffffffu, ss, o);
        mx  = fmaxf(mx, __shfl_xor_sync(0xffffffffu, mx, o));
    }
    float rsd = 1.0f / sqrtf(ss * (1.0f / 256.0f) + 1e-5f);
    if (lane == 0) {
        g_mu[0][row]   = mu;
        g_rstd[0][row] = rsd;
        atomicMax(&sg, __float_as_uint(mx * rsd));
    }
    __syncthreads();
    if (tid == 0) atomicMax(&g_gamma[0], sg);
}

// ---------------- persistent fused layer ----------------------------------
// CTA: 256 threads, 2/SM. B (64KB) loaded ONCE; loop over row-blocks of 64.
// smem: stats 4KB | sgmax | A int8 16KB @4352 | B int8 64KB @20736. 86272 B.
template <int L>
__global__ void __launch_bounds__(256, 2) layer_kernel(const float* __restrict__ xin,
                                                       float* __restrict__ fout) {
    constexpr bool LAST = (L == 2);
    extern __shared__ char smem[];
    int*      risum = (int*)smem;                   // [4][64]
    float*    rsq   = (float*)(smem + 1024);        // [4][64]
    int*      rivx  = (int*)(smem + 2048);          // [4][64]
    int*      rivn  = (int*)(smem + 3072);          // [4][64]
    unsigned* sgmax = (unsigned*)(smem + 4096);
    char*     Asm   = smem + 4352;
    char*     Bsm   = smem + 20736;
    const uint32_t A_u = smem_u32(Asm);
    const uint32_t B_u = smem_u32(Bsm);

    const int tid = threadIdx.x;
    const int warp = tid >> 5, lane = tid & 31;

    if (tid == 0) *sgmax = 0u;

    const float gamma  = fmaxf(__uint_as_float(g_gamma[L]), 1e-8f);
    const float qs     = 127.0f / gamma;
    const float oscale = g_beta[L] * gamma / 127.0f;
    float poscale = 0.f;
    if (L > 0) poscale = g_beta[L - 1] * fmaxf(__uint_as_float(g_gamma[L - 1]), 1e-8f) / 127.0f;

    const short* sprev = (L == 1) ? g_hs1 : g_hs2;
    const float* muL = g_mu[L];
    const float* rsL = g_rstd[L];
    short* outs = (L == 0) ? g_hs1 : g_hs2;

    // ---- B copy ONCE: 64KB pre-swizzled +-1 int8 ----
    {
        const uint4* src = (const uint4*)(g_wb[L]);
        uint4* dst = (uint4*)Bsm;
#pragma unroll
        for (int i = 0; i < 16; ++i) dst[tid + i * 256] = src[tid + i * 256];
    }

    // per-warp constants for the MMA loop
    const int wm = warp & 1;
    const int wn = warp >> 1;
    const unsigned a_ck = (unsigned)(lane >> 4);
    const unsigned b_ck = (unsigned)((lane >> 3) & 1);
    const int qrow = lane >> 2, tig = lane & 3;

    uint32_t b_base[4]; unsigned b_x7[4];
#pragma unroll
    for (int jp = 0; jp < 4; ++jp) {
        int n = wn * 64 + jp * 16 + ((lane >> 4) << 3) + (lane & 7);
        b_base[jp] = B_u + (unsigned)n * 256u;
        b_x7[jp] = (unsigned)n & 7u;
    }
    uint32_t a_base[2]; unsigned a_x7[2];
#pragma unroll
    for (int i = 0; i < 2; ++i) {
        int r = wm * 32 + i * 16 + (lane & 15);
        a_base[i] = A_u + (unsigned)r * 256u;
        a_x7[i] = (unsigned)r & 7u;
    }

    for (int blk = blockIdx.x; blk < NBLK; blk += gridDim.x) {
        const int row0 = blk * 64;

        // ---- A: load -> fused LN+quant -> swizzled smem (16B chunks) ----
#pragma unroll
        for (int it = 0; it < 4; ++it) {
            int c = tid + it * 256;           // 1024 chunks (64 rows x 16)
            int r = c >> 4, ch = c & 15;
            int grow = row0 + r;
            float sc = rsL[grow] * qs;
            float bi = -muL[grow] * sc;
            unsigned pk[4];
            if (L == 0) {
                const float* p = xin + (size_t)grow * DD + ch * 16;
#pragma unroll
                for (int q = 0; q < 4; ++q) {
                    float4 f = *(const float4*)(p + q * 4);
                    unsigned w = 0;
                    float t;
                    t = fminf(fmaxf(fmaf(f.x, sc, bi), -127.f), 127.f);
                    w |= ((unsigned)__float2int_rn(t) & 0xFFu);
                    t = fminf(fmaxf(fmaf(f.y, sc, bi), -127.f), 127.f);
                    w |= ((unsigned)__float2int_rn(t) & 0xFFu) << 8;
                    t = fminf(fmaxf(fmaf(f.z, sc, bi), -127.f), 127.f);
                    w |= ((unsigned)__float2int_rn(t) & 0xFFu) << 16;
                    t = fminf(fmaxf(fmaf(f.w, sc, bi), -127.f), 127.f);
                    w |= ((unsigned)__float2int_rn(t) & 0xFFu) << 24;
                    pk[q] = w;
                }
            } else {
                float sc2 = poscale * sc;
                const short* p = sprev + (size_t)grow * DD + ch * 16;
#pragma unroll
                for (int q = 0; q < 2; ++q) {
                    uint4 u = *(const uint4*)(p + q * 8);
                    unsigned uu[4] = {u.x, u.y, u.z, u.w};
#pragma unroll
                    for (int h = 0; h < 2; ++h) {
                        unsigned w = 0;
#pragma unroll
                        for (int b = 0; b < 2; ++b) {
                            unsigned raw = uu[h * 2 + b];
                            float t0 = fminf(fmaxf(fmaf((float)(short)(raw & 0xFFFF), sc2, bi), -127.f), 127.f);
                            float t1 = fminf(fmaxf(fmaf((float)(short)(raw >> 16),    sc2, bi), -127.f), 127.f);
                            w |= ((unsigned)__float2int_rn(t0) & 0xFFu) << (16 * b);
                            w |= ((unsigned)__float2int_rn(t1) & 0xFFu) << (16 * b + 8);
                        }
                        pk[q * 2 + h] = w;
                    }
                }
            }
            unsigned off = (unsigned)r * 256u + ((((unsigned)ch) ^ ((unsigned)r & 7u)) << 4);
            *(uint4*)(Asm + off) = make_uint4(pk[0], pk[1], pk[2], pk[3]);
        }
        __syncthreads();   // A ready; also protects stats-smem reuse

        // ---- MMA mainloop: warp tile 32(M) x 64(N), K=256 in 8 k32 steps ----
        int acc[2][8][4];
#pragma unroll
        for (int i = 0; i < 2; i++)
#pragma unroll
            for (int j = 0; j < 8; j++)
#pragma unroll
                for (int r = 0; r < 4; r++) acc[i][j][r] = 0;

#pragma unroll
        for (int kk = 0; kk < 8; ++kk) {
            unsigned a[2][4];
#pragma unroll
            for (int i = 0; i < 2; ++i) {
                uint32_t ad = a_base[i] + ((((unsigned)(kk * 2) + a_ck) ^ a_x7[i]) << 4);
                asm volatile("ldmatrix.sync.aligned.m8n8.x4.shared.b16 {%0,%1,%2,%3}, [%4];"
                             : "=r"(a[i][0]), "=r"(a[i][1]), "=r"(a[i][2]), "=r"(a[i][3])
                             : "r"(ad));
            }
#pragma unroll
            for (int jp = 0; jp < 4; ++jp) {
                uint32_t bd = b_base[jp] + ((((unsigned)(kk * 2) + b_ck) ^ b_x7[jp]) << 4);
                unsigned rb[4];
                asm volatile("ldmatrix.sync.aligned.m8n8.x4.shared.b16 {%0,%1,%2,%3}, [%4];"
                             : "=r"(rb[0]), "=r"(rb[1]), "=r"(rb[2]), "=r"(rb[3])
                             : "r"(bd));
#pragma unroll
                for (int i = 0; i < 2; ++i) {
                    asm volatile(
                        "mma.sync.aligned.m16n8k32.row.col.s32.s8.s8.s32 "
                        "{%0,%1,%2,%3}, {%4,%5,%6,%7}, {%8,%9}, {%0,%1,%2,%3};\n"
                        : "+r"(acc[i][2 * jp][0]), "+r"(acc[i][2 * jp][1]),
                          "+r"(acc[i][2 * jp][2]), "+r"(acc[i][2 * jp][3])
                        : "r"(a[i][0]), "r"(a[i][1]), "r"(a[i][2]), "r"(a[i][3]),
                          "r"(rb[0]), "r"(rb[1]));
                    asm volatile(
                        "mma.sync.aligned.m16n8k32.row.col.s32.s8.s8.s32 "
                        "{%0,%1,%2,%3}, {%4,%5,%6,%7}, {%8,%9}, {%0,%1,%2,%3};\n"
                        : "+r"(acc[i][2 * jp + 1][0]), "+r"(acc[i][2 * jp + 1][1]),
                          "+r"(acc[i][2 * jp + 1][2]), "+r"(acc[i][2 * jp + 1][3])
                        : "r"(a[i][0]), "r"(a[i][1]), "r"(a[i][2]), "r"(a[i][3]),
                          "r"(rb[2]), "r"(rb[3]));
                }
            }
        }

        // ---- epilogue ----
#pragma unroll
        for (int i = 0; i < 2; ++i) {
#pragma unroll
            for (int hi = 0; hi < 2; ++hi) {
                int lr = wm * 32 + i * 16 + hi * 8 + qrow;
                int grow = row0 + lr;
                if (!LAST) {
                    int is1 = 0, imx = 0, imn = 0x7fffffff;
                    float s2 = 0.f;
#pragma unroll
                    for (int j = 0; j < 8; ++j) {
                        int q0 = max(acc[i][j][hi * 2], 0);       // exact int <= 32512
                        int q1 = max(acc[i][j][hi * 2 + 1], 0);
                        is1 += q0 + q1;
                        float f0 = (float)q0, f1 = (float)q1;
                        s2 = fmaf(f0, f0, s2);
                        s2 = fmaf(f1, f1, s2);
                        imx = max(imx, max(q0, q1));
                        imn = min(imn, min(q0, q1));
                        int col = wn * 64 + j * 8 + tig * 2;
                        *(unsigned*)(outs + (size_t)grow * DD + col) =
                            (unsigned)(q0 & 0xFFFF) | ((unsigned)q1 << 16);
                    }
                    is1 += __shfl_xor_sync(0xffffffffu, is1, 1);
                    is1 += __shfl_xor_sync(0xffffffffu, is1, 2);
                    s2  += __shfl_xor_sync(0xffffffffu, s2, 1);
                    s2  += __shfl_xor_sync(0xffffffffu, s2, 2);
                    imx  = max(imx, __shfl_xor_sync(0xffffffffu, imx, 1));
                    imx  = max(imx, __shfl_xor_sync(0xffffffffu, imx, 2));
                    imn  = min(imn, __shfl_xor_sync(0xffffffffu, imn, 1));
                    imn  = min(imn, __shfl_xor_sync(0xffffffffu, imn, 2));
                    if (tig == 0) {
                        risum[wn * 64 + lr] = is1;
                        rsq  [wn * 64 + lr] = s2;
                        rivx [wn * 64 + lr] = imx;
                        rivn [wn * 64 + lr] = imn;
                    }
                } else {
#pragma unroll
                    for (int j = 0; j < 8; ++j) {
                        float v0 = (float)acc[i][j][hi * 2]     * oscale;
                        float v1 = (float)acc[i][j][hi * 2 + 1] * oscale;
                        int col = wn * 64 + j * 8 + tig * 2;
                        *(float2*)(fout + (size_t)grow * DD + col) = make_float2(v0, v1);
                    }
                }
            }
        }

        __syncthreads();   // stats ready (non-LAST) / Asm free for next fill

        if constexpr (!LAST) {
            if (tid < 64) {
                int a1i = (risum[tid] + risum[64 + tid]) + (risum[128 + tid] + risum[192 + tid]);
                float a2 = (rsq[tid] + rsq[64 + tid]) + (rsq[128 + tid] + rsq[192 + tid]);
                int mxi = max(max(rivx[tid], rivx[64 + tid]), max(rivx[128 + tid], rivx[192 + tid]));
                int mni = min(min(rivn[tid], rivn[64 + tid]), min(rivn[128 + tid], rivn[192 + tid]));
                float mu  = (float)a1i * oscale * (1.0f / 256.0f);
                float var = fmaxf(a2 * (oscale * oscale) * (1.0f / 256.0f) - mu * mu, 0.0f);
                float rsd = 1.0f / sqrtf(var + 1e-5f);
                g_mu[L + 1][row0 + tid]   = mu;
                g_rstd[L + 1][row0 + tid] = rsd;
                float mx = (float)mxi * oscale, mn = (float)mni * oscale;
                unsigned gu = __float_as_uint(fmaxf(mx - mu, mu - mn) * rsd);
#pragma unroll
                for (int o = 16; o; o >>= 1) gu = max(gu, __shfl_xor_sync(0xffffffffu, gu, o));
                if ((tid & 31) == 0) atomicMax(sgmax, gu);
            }
        }
    }

    if constexpr (!LAST) {
        __syncthreads();
        if (tid == 0) atomicMax(&g_gamma[L + 1], *sgmax);
    }
}

// ---------------- launch ----------------
extern "C" void kernel_launch(void* const* d_in, const int* in_sizes, int n_in,
                              void* d_out, int out_size) {
    const float* x  = (const float*)d_in[0];
    const float* W1 = (const float*)d_in[1];
    const float* W2 = (const float*)d_in[2];
    const float* W3 = (const float*)d_in[3];
    float* out = (float*)d_out;

    int sms = 148;
    cudaDeviceGetAttribute(&sms, cudaDevAttrMultiProcessorCount, 0);
    int pgrid = sms * 2;
    if (pgrid > NBLK) pgrid = NBLK;

    constexpr int SMEM = 20736 + 65536;  // 86272 B
    cudaFuncSetAttribute(layer_kernel<0>, cudaFuncAttributeMaxDynamicSharedMemorySize, SMEM);
    cudaFuncSetAttribute(layer_kernel<1>, cudaFuncAttributeMaxDynamicSharedMemorySize, SMEM);
    cudaFuncSetAttribute(layer_kernel<2>, cudaFuncAttributeMaxDynamicSharedMemorySize, SMEM);

    init_kernel<<<1, 32>>>();
    wprep_kernel<<<3, 1024>>>(W1, W2, W3);
    stats_kernel<<<BN / 8, 256>>>(x);
    layer_kernel<0><<<pgrid, 256, SMEM>>>(x, nullptr);
    layer_kernel<1><<<pgrid, 256, SMEM>>>(nullptr, nullptr);
    layer_kernel<2><<<pgrid, 256, SMEM>>>(nullptr, out);
}

// round 14
// speedup vs baseline: 1.1398x; 1.1398x over previous
#include <cuda_runtime.h>
#include <cuda_bf16.h>
#include <math.h>
#include <stdint.h>

#define BN 131072
#define DD 256
#define NBLK (BN / 64)

// ---------------- scratch (device globals: allocation-free) ----------------
__device__ __align__(16) short       g_hs1[(size_t)BN * DD];   // layer0 out (int16, exact)
__device__ __align__(16) short       g_hs2[(size_t)BN * DD];   // layer1 out
__device__ float                     g_mu[3][BN];
__device__ float                     g_rstd[3][BN];
__device__ unsigned                  g_gamma[3];
__device__ float                     g_beta[3];
__device__ __align__(16) signed char g_wb[3][DD * DD];         // +-1 int8, swizzled [n][k] layout

__device__ __forceinline__ uint32_t smem_u32(const void* p) {
    uint32_t a;
    asm("{ .reg .u64 t; cvta.to.shared.u64 t, %1; cvt.u32.u64 %0, t; }" : "=r"(a) : "l"(p));
    return a;
}

#define MBAR_INIT(mb, c) asm volatile("mbarrier.init.shared.b64 [%0], %1;" :: "r"(mb), "r"(c) : "memory")

#define MBAR_WAIT(mbar_smem_addr, phase_parity) do {                                         \
    uint32_t _mbar = (uint32_t)(mbar_smem_addr);                                             \
    uint32_t _parity = (uint32_t)(phase_parity);                                             \
    uint32_t _done;                                                                          \
    asm volatile(                                                                            \
        "{\n\t.reg .pred p;\n\t"                                                             \
        "mbarrier.try_wait.parity.shared.b64 p, [%1], %2;\n\t"                               \
        "selp.b32 %0, 1, 0, p;\n\t}"                                                         \
        : "=r"(_done) : "r"(_mbar), "r"(_parity) : "memory");                                \
    if (!_done) {                                                                            \
        asm volatile(                                                                        \
            "{\n\t.reg .pred P1;\n\t"                                                        \
            "WAIT_LOOP_%=:\n\t"                                                              \
            "mbarrier.try_wait.parity.shared.b64 P1, [%0], %1;\n\t"                          \
            "@P1 bra.uni WAIT_DONE_%=;\n\t"                                                  \
            "bra.uni WAIT_LOOP_%=;\n\t"                                                      \
            "WAIT_DONE_%=:\n\t}"                                                             \
            :: "r"(_mbar), "r"(_parity) : "memory");                                         \
    }                                                                                        \
} while (0)

// ---------------- init ----------------
__global__ void init_kernel() {
    if (threadIdx.x < 3) g_gamma[threadIdx.x] = 0u;
}

// ---------------- weight prep: alpha/beta + sign -> swizzled int8 ---------
// Layout: row n (256 B of k), chunk c (16B) stored at chunk (c ^ (n&7)).
__global__ void __launch_bounds__(1024) wprep_kernel(const float* __restrict__ W1,
                                                     const float* __restrict__ W2,
                                                     const float* __restrict__ W3) {
    const float* W = blockIdx.x == 0 ? W1 : (blockIdx.x == 1 ? W2 : W3);
    __shared__ float ps[32], pa[32];
    __shared__ float s_alpha;
    int tid = threadIdx.x;
    float s = 0.f, sa = 0.f;
    for (int i = tid; i < DD * DD; i += 1024) {
        float w = W[i];
        s += w; sa += fabsf(w);
    }
#pragma unroll
    for (int o = 16; o; o >>= 1) {
        s  += __shfl_xor_sync(0xffffffffu, s,  o);
        sa += __shfl_xor_sync(0xffffffffu, sa, o);
    }
    if ((tid & 31) == 0) { ps[tid >> 5] = s; pa[tid >> 5] = sa; }
    __syncthreads();
    if (tid == 0) {
        float ts = 0.f, ta = 0.f;
        for (int i = 0; i < 32; i++) { ts += ps[i]; ta += pa[i]; }  // fixed order
        float alpha = ts / 65536.0f;
        g_beta[blockIdx.x] = fmaxf(ta / 65536.0f, 1e-8f);
        s_alpha = alpha;
    }
    __syncthreads();
    float alpha = s_alpha;
    signed char* wb = g_wb[blockIdx.x];
    for (int i = tid; i < DD * DD; i += 1024) {
        int n = i >> 8, k = i & 255;
        signed char v = ((W[i] - alpha) > 0.f) ? (signed char)1 : (signed char)-1;
        unsigned off = (unsigned)n * 256u + ((((unsigned)k >> 4) ^ ((unsigned)n & 7u)) << 4) + ((unsigned)k & 15u);
        wb[off] = v;
    }
}

// ---------------- stats for x: per-row mu/rstd + global gamma[0] ----------
__global__ void __launch_bounds__(256) stats_kernel(const float* __restrict__ x) {
    __shared__ unsigned sg;
    int tid = threadIdx.x;
    if (tid == 0) sg = 0u;
    __syncthreads();
    int warp = tid >> 5, lane = tid & 31;
    size_t row = (size_t)blockIdx.x * 8 + warp;
    const float* xr = x + row * DD;
    float4 a = *(const float4*)(xr + lane * 4);
    float4 b = *(const float4*)(xr + 128 + lane * 4);
    float s = ((a.x + a.y) + (a.z + a.w)) + ((b.x + b.y) + (b.z + b.w));
#pragma unroll
    for (int o = 16; o; o >>= 1) s += __shfl_xor_sync(0xffffffffu, s, o);
    float mu = s * (1.0f / 256.0f);
    float ss = 0.f, mx = 0.f, d;
    d = a.x - mu; ss += d * d; mx = fmaxf(mx, fabsf(d));
    d = a.y - mu; ss += d * d; mx = fmaxf(mx, fabsf(d));
    d = a.z - mu; ss += d * d; mx = fmaxf(mx, fabsf(d));
    d = a.w - mu; ss += d * d; mx = fmaxf(mx, fabsf(d));
    d = b.x - mu; ss += d * d; mx = fmaxf(mx, fabsf(d));
    d = b.y - mu; ss += d * d; mx = fmaxf(mx, fabsf(d));
    d = b.z - mu; ss += d * d; mx = fmaxf(mx, fabsf(d));
    d = b.w - mu; ss += d * d; mx = fmaxf(mx, fabsf(d));
#pragma unroll
    for (int o = 16; o; o >>= 1) {
        ss += __shfl_xor_sync(0xffffffffu, ss, o);
        mx  = fmaxf(mx, __shfl_xor_sync(0xffffffffu, mx, o));
    }
    float rsd = 1.0f / sqrtf(ss * (1.0f / 256.0f) + 1e-5f);
    if (lane == 0) {
        g_mu[0][row]   = mu;
        g_rstd[0][row] = rsd;
        atomicMax(&sg, __float_as_uint(mx * rsd));
    }
    __syncthreads();
    if (tid == 0) atomicMax(&g_gamma[0], sg);
}

// ---------------- fused layer: LN+quant -> IMMA (ldmatrix) -> epilogue ----
// CTA: 64 rows x 256 cols, K=256. 256 threads = 8 warps (2M x 4N), warp 32x64.
// B arrives via cp.async.bulk (overlaps A-fill). 2 CTAs / SM.
// smem: stats 4KB | sgmax | mbar | A int8 16KB @4352 | B int8 64KB @20736. 86272 B.
template <int L>
__global__ void __launch_bounds__(256, 2) layer_kernel(const float* __restrict__ xin,
                                                       float* __restrict__ fout) {
    constexpr bool LAST = (L == 2);
    extern __shared__ char smem[];
    int*      risum = (int*)smem;                   // [4][64]
    float*    rsq   = (float*)(smem + 1024);        // [4][64]
    int*      rivx  = (int*)(smem + 2048);          // [4][64]
    int*      rivn  = (int*)(smem + 3072);          // [4][64]
    unsigned* sgmax = (unsigned*)(smem + 4096);
    char*     Asm   = smem + 4352;
    char*     Bsm   = smem + 20736;
    const uint32_t A_u  = smem_u32(Asm);
    const uint32_t B_u  = smem_u32(Bsm);
    const uint32_t MBAR = smem_u32(smem + 4104);

    const int tid = threadIdx.x;
    const int warp = tid >> 5, lane = tid & 31;
    const int row0 = blockIdx.x * 64;

    // ---- B: single-thread async bulk copy (overlaps the A-fill below) ----
    if (tid == 0) {
        *sgmax = 0u;
        MBAR_INIT(MBAR, 1);
        asm volatile("mbarrier.arrive.expect_tx.shared.b64 _, [%0], %1;"
                     :: "r"(MBAR), "r"(65536u) : "memory");
        asm volatile("cp.async.bulk.shared::cta.global.mbarrier::complete_tx::bytes "
                     "[%0], [%1], %2, [%3];"
                     :: "r"(B_u), "l"((const void*)g_wb[L]), "r"(65536u), "r"(MBAR)
                     : "memory");
    }

    const float gamma  = fmaxf(__uint_as_float(g_gamma[L]), 1e-8f);
    const float qs     = 127.0f / gamma;
    const float oscale = g_beta[L] * gamma / 127.0f;
    float poscale = 0.f;
    if (L > 0) poscale = g_beta[L - 1] * fmaxf(__uint_as_float(g_gamma[L - 1]), 1e-8f) / 127.0f;

    const short* sprev = (L == 1) ? g_hs1 : g_hs2;
    const float* muL = g_mu[L];
    const float* rsL = g_rstd[L];
    short* outs = (L == 0) ? g_hs1 : g_hs2;

    // ---- A: load -> fused LN+quant -> swizzled smem (16B chunks) ----
#pragma unroll
    for (int it = 0; it < 4; ++it) {
        int c = tid + it * 256;           // 1024 chunks (64 rows x 16)
        int r = c >> 4, ch = c & 15;
        int grow = row0 + r;
        float sc = rsL[grow] * qs;
        float bi = -muL[grow] * sc;
        unsigned pk[4];
        if (L == 0) {
            const float* p = xin + (size_t)grow * DD + ch * 16;
#pragma unroll
            for (int q = 0; q < 4; ++q) {
                float4 f = *(const float4*)(p + q * 4);
                unsigned w = 0;
                float t;
                t = fminf(fmaxf(fmaf(f.x, sc, bi), -127.f), 127.f);
                w |= ((unsigned)__float2int_rn(t) & 0xFFu);
                t = fminf(fmaxf(fmaf(f.y, sc, bi), -127.f), 127.f);
                w |= ((unsigned)__float2int_rn(t) & 0xFFu) << 8;
                t = fminf(fmaxf(fmaf(f.z, sc, bi), -127.f), 127.f);
                w |= ((unsigned)__float2int_rn(t) & 0xFFu) << 16;
                t = fminf(fmaxf(fmaf(f.w, sc, bi), -127.f), 127.f);
                w |= ((unsigned)__float2int_rn(t) & 0xFFu) << 24;
                pk[q] = w;
            }
        } else {
            float sc2 = poscale * sc;
            const short* p = sprev + (size_t)grow * DD + ch * 16;
#pragma unroll
            for (int q = 0; q < 2; ++q) {
                uint4 u = *(const uint4*)(p + q * 8);
                unsigned uu[4] = {u.x, u.y, u.z, u.w};
#pragma unroll
                for (int h = 0; h < 2; ++h) {
                    unsigned w = 0;
#pragma unroll
                    for (int b = 0; b < 2; ++b) {
                        unsigned raw = uu[h * 2 + b];
                        float t0 = fminf(fmaxf(fmaf((float)(short)(raw & 0xFFFF), sc2, bi), -127.f), 127.f);
                        float t1 = fminf(fmaxf(fmaf((float)(short)(raw >> 16),    sc2, bi), -127.f), 127.f);
                        w |= ((unsigned)__float2int_rn(t0) & 0xFFu) << (16 * b);
                        w |= ((unsigned)__float2int_rn(t1) & 0xFFu) << (16 * b + 8);
                    }
                    pk[q * 2 + h] = w;
                }
            }
        }
        unsigned off = (unsigned)r * 256u + ((((unsigned)ch) ^ ((unsigned)r & 7u)) << 4);
        *(uint4*)(Asm + off) = make_uint4(pk[0], pk[1], pk[2], pk[3]);
    }
    __syncthreads();        // A visible to all warps (and MBAR init to all threads)
    MBAR_WAIT(MBAR, 0);     // B bulk copy complete

    // ---- MMA mainloop: warp tile 32(M) x 64(N), K=256 in 8 k32 steps ----
    const int wm = warp & 1;        // 2 M-groups of 32 rows
    const int wn = warp >> 1;       // 4 N-groups of 64 cols

    uint32_t a_base[2]; unsigned a_x7[2];
#pragma unroll
    for (int i = 0; i < 2; ++i) {
        int r = wm * 32 + i * 16 + (lane & 15);
        a_base[i] = A_u + (unsigned)r * 256u;
        a_x7[i] = (unsigned)r & 7u;
    }
    uint32_t b_base[4]; unsigned b_x7[4];
#pragma unroll
    for (int jp = 0; jp < 4; ++jp) {
        int n = wn * 64 + jp * 16 + ((lane >> 4) << 3) + (lane & 7);
        b_base[jp] = B_u + (unsigned)n * 256u;
        b_x7[jp] = (unsigned)n & 7u;
    }
    const unsigned a_ck = (unsigned)(lane >> 4);        // 0/1: k16-half
    const unsigned b_ck = (unsigned)((lane >> 3) & 1);  // 0/1

    int acc[2][8][4];
#pragma unroll
    for (int i = 0; i < 2; i++)
#pragma unroll
        for (int j = 0; j < 8; j++)
#pragma unroll
            for (int r = 0; r < 4; r++) acc[i][j][r] = 0;

#pragma unroll
    for (int kk = 0; kk < 8; ++kk) {
        unsigned a[2][4];
#pragma unroll
        for (int i = 0; i < 2; ++i) {
            uint32_t ad = a_base[i] + ((((unsigned)(kk * 2) + a_ck) ^ a_x7[i]) << 4);
            asm volatile("ldmatrix.sync.aligned.m8n8.x4.shared.b16 {%0,%1,%2,%3}, [%4];"
                         : "=r"(a[i][0]), "=r"(a[i][1]), "=r"(a[i][2]), "=r"(a[i][3])
                         : "r"(ad));
        }
#pragma unroll
        for (int jp = 0; jp < 4; ++jp) {
            uint32_t bd = b_base[jp] + ((((unsigned)(kk * 2) + b_ck) ^ b_x7[jp]) << 4);
            unsigned rb[4];
            asm volatile("ldmatrix.sync.aligned.m8n8.x4.shared.b16 {%0,%1,%2,%3}, [%4];"
                         : "=r"(rb[0]), "=r"(rb[1]), "=r"(rb[2]), "=r"(rb[3])
                         : "r"(bd));
#pragma unroll
            for (int i = 0; i < 2; ++i) {
                asm volatile(
                    "mma.sync.aligned.m16n8k32.row.col.s32.s8.s8.s32 "
                    "{%0,%1,%2,%3}, {%4,%5,%6,%7}, {%8,%9}, {%0,%1,%2,%3};\n"
                    : "+r"(acc[i][2 * jp][0]), "+r"(acc[i][2 * jp][1]),
                      "+r"(acc[i][2 * jp][2]), "+r"(acc[i][2 * jp][3])
                    : "r"(a[i][0]), "r"(a[i][1]), "r"(a[i][2]), "r"(a[i][3]),
                      "r"(rb[0]), "r"(rb[1]));
                asm volatile(
                    "mma.sync.aligned.m16n8k32.row.col.s32.s8.s8.s32 "
                    "{%0,%1,%2,%3}, {%4,%5,%6,%7}, {%8,%9}, {%0,%1,%2,%3};\n"
                    : "+r"(acc[i][2 * jp + 1][0]), "+r"(acc[i][2 * jp + 1][1]),
                      "+r"(acc[i][2 * jp + 1][2]), "+r"(acc[i][2 * jp + 1][3])
                    : "r"(a[i][0]), "r"(a[i][1]), "r"(a[i][2]), "r"(a[i][3]),
                      "r"(rb[2]), "r"(rb[3]));
            }
        }
    }

    // ---- epilogue: relu+store int16, integer stats for next-layer LN ----
    const int qrow = lane >> 2, tig = lane & 3;

#pragma unroll
    for (int i = 0; i < 2; ++i) {
#pragma unroll
        for (int hi = 0; hi < 2; ++hi) {
            int lr = wm * 32 + i * 16 + hi * 8 + qrow;
            int grow = row0 + lr;
            if (!LAST) {
                int is1 = 0, imx = 0, imn = 0x7fffffff;
                float s2 = 0.f;
#pragma unroll
                for (int j = 0; j < 8; ++j) {
                    int q0 = max(acc[i][j][hi * 2], 0);       // exact int <= 32512
                    int q1 = max(acc[i][j][hi * 2 + 1], 0);
                    is1 += q0 + q1;
                    float f0 = (float)q0, f1 = (float)q1;
                    s2 = fmaf(f0, f0, s2);
                    s2 = fmaf(f1, f1, s2);
                    imx = max(imx, max(q0, q1));
                    imn = min(imn, min(q0, q1));
                    int col = wn * 64 + j * 8 + tig * 2;
                    *(unsigned*)(outs + (size_t)grow * DD + col) =
                        (unsigned)(q0 & 0xFFFF) | ((unsigned)q1 << 16);
                }
                is1 += __shfl_xor_sync(0xffffffffu, is1, 1);
                is1 += __shfl_xor_sync(0xffffffffu, is1, 2);
                s2  += __shfl_xor_sync(0xffffffffu, s2, 1);
                s2  += __shfl_xor_sync(0xffffffffu, s2, 2);
                imx  = max(imx, __shfl_xor_sync(0xffffffffu, imx, 1));
                imx  = max(imx, __shfl_xor_sync(0xffffffffu, imx, 2));
                imn  = min(imn, __shfl_xor_sync(0xffffffffu, imn, 1));
                imn  = min(imn, __shfl_xor_sync(0xffffffffu, imn, 2));
                if (tig == 0) {
                    risum[wn * 64 + lr] = is1;
                    rsq  [wn * 64 + lr] = s2;
                    rivx [wn * 64 + lr] = imx;
                    rivn [wn * 64 + lr] = imn;
                }
            } else {
#pragma unroll
                for (int j = 0; j < 8; ++j) {
                    float v0 = (float)acc[i][j][hi * 2]     * oscale;
                    float v1 = (float)acc[i][j][hi * 2 + 1] * oscale;
                    int col = wn * 64 + j * 8 + tig * 2;
                    *(float2*)(fout + (size_t)grow * DD + col) = make_float2(v0, v1);
                }
            }
        }
    }

    if constexpr (!LAST) {
        __syncthreads();
        if (tid < 64) {
            int a1i = (risum[tid] + risum[64 + tid]) + (risum[128 + tid] + risum[192 + tid]);
            float a2 = (rsq[tid] + rsq[64 + tid]) + (rsq[128 + tid] + rsq[192 + tid]);
            int mxi = max(max(rivx[tid], rivx[64 + tid]), max(rivx[128 + tid], rivx[192 + tid]));
            int mni = min(min(rivn[tid], rivn[64 + tid]), min(rivn[128 + tid], rivn[192 + tid]));
            float mu  = (float)a1i * oscale * (1.0f / 256.0f);
            float var = fmaxf(a2 * (oscale * oscale) * (1.0f / 256.0f) - mu * mu, 0.0f);
            float rsd = 1.0f / sqrtf(var + 1e-5f);
            g_mu[L + 1][row0 + tid]   = mu;
            g_rstd[L + 1][row0 + tid] = rsd;
            float mx = (float)mxi * oscale, mn = (float)mni * oscale;
            unsigned gu = __float_as_uint(fmaxf(mx - mu, mu - mn) * rsd);
#pragma unroll
            for (int o = 16; o; o >>= 1) gu = max(gu, __shfl_xor_sync(0xffffffffu, gu, o));
            if ((tid & 31) == 0) atomicMax(sgmax, gu);
        }
        __syncthreads();
        if (tid == 0) atomicMax(&g_gamma[L + 1], *sgmax);
    }
}

// ---------------- launch ----------------
extern "C" void kernel_launch(void* const* d_in, const int* in_sizes, int n_in,
                              void* d_out, int out_size) {
    const float* x  = (const float*)d_in[0];
    const float* W1 = (const float*)d_in[1];
    const float* W2 = (const float*)d_in[2];
    const float* W3 = (const float*)d_in[3];
    float* out = (float*)d_out;

    constexpr int SMEM = 20736 + 65536;  // 86272 B
    cudaFuncSetAttribute(layer_kernel<0>, cudaFuncAttributeMaxDynamicSharedMemorySize, SMEM);
    cudaFuncSetAttribute(layer_kernel<1>, cudaFuncAttributeMaxDynamicSharedMemorySize, SMEM);
    cudaFuncSetAttribute(layer_kernel<2>, cudaFuncAttributeMaxDynamicSharedMemorySize, SMEM);

    init_kernel<<<1, 32>>>();
    wprep_kernel<<<3, 1024>>>(W1, W2, W3);
    stats_kernel<<<BN / 8, 256>>>(x);
    layer_kernel<0><<<NBLK, 256, SMEM>>>(x, nullptr);
    layer_kernel<1><<<NBLK, 256, SMEM>>>(nullptr, nullptr);
    layer_kernel<2><<<NBLK, 256, SMEM>>>(nullptr, out);
}